// round 9
// baseline (speedup 1.0000x reference)
#include <cuda_runtime.h>
#include <math.h>

#define MAXN 204800
#define NB   4
#define KTOP 1024
#define ECAP 4096

__device__ unsigned int       g_score[MAXN];
__device__ float              g_boxes[MAXN][8];   // x,y,z,l,w,h,ang,score
__device__ unsigned long long g_list[NB][MAXN];
__device__ int                g_cnt[NB];
__device__ float              g_sel[NB][KTOP][8];

__global__ void k_init() {
    if (threadIdx.x < NB) g_cnt[threadIdx.x] = 0;
}

// ---------------- GEMV: warp per point, weights in registers ----------------
// launch_bounds(256,1): 256 regs/thread -> weights (80 f32/lane) stay in
// registers, no spills. Depth-2 software pipeline covers DRAM latency.
// Score sigmoids in fp64: correctly-rounded fp32 score reproduces the
// reference top-k ordering exactly (fp32 expf caused rank swaps -> 1.3e-2).
__global__ void __launch_bounds__(256, 1) k_gemv(
    const float* __restrict__ feat, const int* __restrict__ coor,
    const float* __restrict__ Wc, const float* __restrict__ bc,
    const float* __restrict__ Wr, const float* __restrict__ br, int N)
{
    const int lane = threadIdx.x & 31;
    const int warp = (blockIdx.x * blockDim.x + threadIdx.x) >> 5;
    const int nw   = (gridDim.x * blockDim.x) >> 5;

    // lane owns rows {lane*4+t} (t<4) and {128+lane*4+(t-4)} (t>=4)
    int rows[8];
#pragma unroll
    for (int t = 0; t < 8; t++) rows[t] = (t < 4) ? (lane * 4 + t) : (128 + lane * 4 + t - 4);

    float wd[8], wr[8][9];
#pragma unroll
    for (int t = 0; t < 8; t++) {
        wd[t] = Wc[rows[t] * 2 + 1] - Wc[rows[t] * 2 + 0];
#pragma unroll
        for (int j = 0; j < 9; j++) wr[t][j] = Wr[rows[t] * 9 + j];
    }
    const float db = bc[1] - bc[0];
    float brv[9];
#pragma unroll
    for (int j = 0; j < 9; j++) brv[j] = br[j];

    const int nw2 = nw * 2;
    float4 a0 = make_float4(0, 0, 0, 0), b0 = a0, a1 = a0, b1 = a0;
    if (warp < N) {
        const float4* f4 = (const float4*)(feat + (size_t)warp * 256);
        a0 = f4[lane]; b0 = f4[32 + lane];
    }
    if (warp + nw < N) {
        const float4* f4 = (const float4*)(feat + (size_t)(warp + nw) * 256);
        a1 = f4[lane]; b1 = f4[32 + lane];
    }

    for (int p = warp; p < N; p += nw) {
        int p2 = p + nw2;
        float4 a2 = make_float4(0, 0, 0, 0), b2 = a2;
        if (p2 < N) {
            const float4* f4 = (const float4*)(feat + (size_t)p2 * 256);
            a2 = f4[lane]; b2 = f4[32 + lane];
        }
        float fv[8] = {a0.x, a0.y, a0.z, a0.w, b0.x, b0.y, b0.z, b0.w};
        float acc[10];
#pragma unroll
        for (int j = 0; j < 10; j++) acc[j] = 0.f;
#pragma unroll
        for (int t = 0; t < 8; t++) {
            acc[0] = fmaf(fv[t], wd[t], acc[0]);
#pragma unroll
            for (int j = 0; j < 9; j++) acc[1 + j] = fmaf(fv[t], wr[t][j], acc[1 + j]);
        }
#pragma unroll
        for (int j = 0; j < 10; j++) {
#pragma unroll
            for (int o = 16; o > 0; o >>= 1)
                acc[j] += __shfl_xor_sync(0xFFFFFFFFu, acc[j], o);
        }
        if (lane == 0) {
            float dl = acc[0] + db;
            float rg[9];
#pragma unroll
            for (int j = 0; j < 9; j++) rg[j] = acc[1 + j] + brv[j];
            double sd = 1.0 / (1.0 + exp(-(double)dl));
            double ss = 1.0 / (1.0 + exp(-(double)rg[8]));
            float score = (float)(sd * ss);
            float cx = (float)coor[2 * p]     * 0.8f + rg[0];
            float cy = (float)coor[2 * p + 1] * 0.8f + rg[1];
            float bl = expf(fminf(fmaxf(rg[3], -6.f), 6.f));
            float bw = expf(fminf(fmaxf(rg[4], -6.f), 6.f));
            float bh = expf(fminf(fmaxf(rg[5], -6.f), 6.f));
            float an = atan2f(rg[6], rg[7]);
            float* bx = g_boxes[p];
            bx[0] = cx; bx[1] = cy; bx[2] = rg[2]; bx[3] = bl;
            bx[4] = bw; bx[5] = bh; bx[6] = an;  bx[7] = score;
            g_score[p] = __float_as_uint(score);
        }
        a0 = a1; b0 = b1; a1 = a2; b1 = b2;
    }
}

// ---------------- per-batch compaction ----------------
__global__ void k_compact(const int* __restrict__ bidx, int N)
{
    __shared__ int c[NB], base[NB];
    int t = threadIdx.x;
    if (t < NB) c[t] = 0;
    __syncthreads();
    int p = blockIdx.x * 1024 + t;
    int b = 0, r = 0;
    if (p < N) { b = bidx[p]; r = atomicAdd(&c[b], 1); }
    __syncthreads();
    if (t < NB) base[t] = atomicAdd(&g_cnt[t], c[t]);
    __syncthreads();
    if (p < N) {
        unsigned long long key =
            ((unsigned long long)g_score[p] << 32) | (unsigned)(~(unsigned)p);
        g_list[b][base[b] + r] = key;
    }
}

// ---------------- exact radix select top-1024 + bitonic sort ----------------
__global__ void k_select()
{
    const int b = blockIdx.x, tid = threadIdx.x;
    __shared__ unsigned int       hist[2048];
    __shared__ unsigned long long keys[KTOP];
    __shared__ unsigned long long sh_lo;
    __shared__ int sh_need, sh_done, sh_bin, sh_cnt;

    const int cnt = g_cnt[b];
    if (tid == 0) {
        sh_lo = 0ull; sh_need = KTOP; sh_cnt = 0;
        sh_done = (cnt <= KTOP) ? 1 : 0;
    }
    const int shifts[6] = {53, 42, 31, 20, 9, 0};
    const int widths[6] = {11, 11, 11, 11, 11, 9};

    for (int pass = 0; pass < 6; pass++) {
        __syncthreads();
        if (sh_done) break;
        for (int i = tid; i < 2048; i += 1024) hist[i] = 0;
        __syncthreads();
        const int shift = shifts[pass], w = widths[pass];
        const int nb = 1 << w;
        const unsigned long long hm =
            (shift + w >= 64) ? 0ull : ~((1ull << (shift + w)) - 1ull);
        const unsigned long long lo = sh_lo;
        const int need = sh_need;
        const unsigned mask = (unsigned)(nb - 1);
        for (int e = tid; e < cnt; e += 1024) {
            unsigned long long kk = g_list[b][e];
            if ((kk & hm) == lo)
                atomicAdd(&hist[(unsigned)(kk >> shift) & mask], 1u);
        }
        __syncthreads();
        for (int d = 1; d < nb; d <<= 1) {     // suffix sums
            unsigned v0 = 0, v1 = 0;
            int i0 = tid, i1 = tid + 1024;
            if (i0 < nb) v0 = hist[i0] + ((i0 + d < nb) ? hist[i0 + d] : 0u);
            if (i1 < nb) v1 = hist[i1] + ((i1 + d < nb) ? hist[i1 + d] : 0u);
            __syncthreads();
            if (i0 < nb) hist[i0] = v0;
            if (i1 < nb) hist[i1] = v1;
            __syncthreads();
        }
        for (int i = tid; i < nb; i += 1024) {
            unsigned s  = hist[i];
            unsigned sn = (i + 1 < nb) ? hist[i + 1] : 0u;
            if (s >= (unsigned)need && sn < (unsigned)need) sh_bin = i;
        }
        __syncthreads();
        if (tid == 0) {
            int bin = sh_bin;
            unsigned above = (bin + 1 < nb) ? hist[bin + 1] : 0u;
            unsigned cb = hist[bin] - above;
            sh_lo = lo | ((unsigned long long)bin << shift);
            int nd = need - (int)above;
            sh_need = nd;
            if ((unsigned)nd == cb) sh_done = 1;
        }
    }
    __syncthreads();
    const unsigned long long T = sh_lo;
    for (int e = tid; e < cnt; e += 1024) {
        unsigned long long kk = g_list[b][e];
        if (kk >= T) {
            int pos = atomicAdd(&sh_cnt, 1);
            if (pos < KTOP) keys[pos] = ~kk;    // inverted -> ascending == score desc
        }
    }
    __syncthreads();
    for (int i = tid; i < KTOP; i += 1024)
        if (i >= sh_cnt) keys[i] = ~0ull;
    __syncthreads();
    for (int k2 = 2; k2 <= KTOP; k2 <<= 1) {
        for (int j = k2 >> 1; j > 0; j >>= 1) {
            int ixj = tid ^ j;
            if (ixj > tid) {
                unsigned long long a = keys[tid], c2 = keys[ixj];
                bool up = ((tid & k2) == 0);
                if (up ? (a > c2) : (a < c2)) { keys[tid] = c2; keys[ixj] = a; }
            }
            __syncthreads();
        }
    }
    unsigned long long kv = ~keys[tid];
    float* o = g_sel[b][tid];
    if (kv != 0ull) {
        unsigned p = ~(unsigned)(kv & 0xFFFFFFFFull);
        const float* bx = g_boxes[p];
#pragma unroll
        for (int c2 = 0; c2 < 8; c2++) o[c2] = bx[c2];
    } else {
#pragma unroll
        for (int c2 = 0; c2 < 8; c2++) o[c2] = 0.f;
    }
}

__global__ void k_zero(float* out, int n) {
    int i = blockIdx.x * blockDim.x + threadIdx.x;
    if (i < n) out[i] = 0.f;
}

// ---------------- sparse-edge NMS + output assembly ----------------
__global__ void k_nms(float* __restrict__ out, int out_size)
{
    const int b = blockIdx.x, tid = threadIdx.x;
    __shared__ float sx1[KTOP], sx2[KTOP], sy1[KTOP], sy2[KTOP], sar[KTOP];
    __shared__ unsigned int edges[ECAP];
    __shared__ unsigned int suppw[KTOP / 32];
    __shared__ int ecnt;

    if (tid == 0) ecnt = 0;
    const float* s = g_sel[b][tid];
    float x = s[0], y = s[1], l = s[3], w = s[4];
    sx1[tid] = x - l * 0.5f; sx2[tid] = x + l * 0.5f;
    sy1[tid] = y - w * 0.5f; sy2[tid] = y + w * 0.5f;
    sar[tid] = l * w;
    __syncthreads();

    const float ax1 = sx1[tid], ax2 = sx2[tid];
    const float ay1 = sy1[tid], ay2 = sy2[tid], aa = sar[tid];
    for (int j = tid + 1; j < KTOP; j++) {
        float ix = fminf(ax2, sx2[j]) - fmaxf(ax1, sx1[j]);
        float iy = fminf(ay2, sy2[j]) - fmaxf(ay1, sy1[j]);
        ix = fmaxf(ix, 0.f); iy = fmaxf(iy, 0.f);
        float inter = ix * iy;
        float uni = aa + sar[j] - inter;
        float iou = inter / fmaxf(uni, 1e-6f);
        if (iou > 0.1f) {
            int e = atomicAdd(&ecnt, 1);
            if (e < ECAP) edges[e] = ((unsigned)tid << 10) | (unsigned)j;
        }
    }
    __syncthreads();
    if (tid == 0) {
        int E = ecnt < ECAP ? ecnt : ECAP;
        for (int i = 1; i < E; i++) {       // insertion sort (E ~ tens)
            unsigned v = edges[i]; int k = i - 1;
            while (k >= 0 && edges[k] > v) { edges[k + 1] = edges[k]; k--; }
            edges[k + 1] = v;
        }
        unsigned sw[KTOP / 32];
#pragma unroll
        for (int i2 = 0; i2 < KTOP / 32; i2++) sw[i2] = 0u;
        for (int e = 0; e < E; e++) {
            unsigned v = edges[e];
            int i2 = v >> 10, j2 = v & 1023;
            if (!((sw[i2 >> 5] >> (i2 & 31)) & 1u))
                sw[j2 >> 5] |= 1u << (j2 & 31);
        }
#pragma unroll
        for (int i2 = 0; i2 < KTOP / 32; i2++) suppw[i2] = sw[i2];
    }
    __syncthreads();
    bool keep = !((suppw[tid >> 5] >> (tid & 31)) & 1u);
    float km = keep ? 1.f : 0.f;
    int row = b * KTOP + tid;
    int obase = row * 8;
    if (obase + 7 < out_size) {
#pragma unroll
        for (int c = 0; c < 8; c++) out[obase + c] = s[c] * km;
    }
    int lb_i = NB * KTOP * 8 + row;
    int kp_i = NB * KTOP * 9 + row;
    if (lb_i < out_size) out[lb_i] = 0.f;
    if (kp_i < out_size) out[kp_i] = km;
}

extern "C" void kernel_launch(void* const* d_in, const int* in_sizes, int n_in,
                              void* d_out, int out_size)
{
    const float* feat = (const float*)d_in[0];
    const int*   bidx = (const int*)d_in[1];
    const int*   coor = (const int*)d_in[2];
    const float* Wc   = (const float*)d_in[3];
    const float* bc   = (const float*)d_in[4];
    const float* Wr   = (const float*)d_in[5];
    const float* br   = (const float*)d_in[6];
    float* out = (float*)d_out;
    int N = in_sizes[1];

    k_init<<<1, 32>>>();
    k_gemv<<<148, 256>>>(feat, coor, Wc, bc, Wr, br, N);
    k_compact<<<(N + 1023) / 1024, 1024>>>(bidx, N);
    k_select<<<NB, 1024>>>();
    k_zero<<<(out_size + 255) / 256, 256>>>(out, out_size);
    k_nms<<<NB, 1024>>>(out, out_size);
}

// round 10
// speedup vs baseline: 2.4165x; 2.4165x over previous
#include <cuda_runtime.h>
#include <math.h>

#define MAXN 204800
#define NB   4
#define KTOP 1024
#define ECAP 4096

__device__ float              g_raw[MAXN][10];    // raw GEMV sums
__device__ unsigned int       g_score[MAXN];
__device__ float              g_boxes[MAXN][8];   // x,y,z,l,w,h,ang,score
__device__ unsigned long long g_list[NB][MAXN];
__device__ int                g_cnt[NB];
__device__ float              g_sel[NB][KTOP][8];

__global__ void k_init() {
    if (threadIdx.x < NB) g_cnt[threadIdx.x] = 0;
}

// ---------------- pure GEMV: warp per point, weights in registers ----------
// No transcendentals, no fp64, no lane-0 latency tail: just loads, FMA,
// shfl-tree reduce, and a 40B store. Accumulation order identical to the
// passing R4/R9 kernels (score path must stay bit-exact).
__global__ void __launch_bounds__(256, 2) k_gemv(
    const float* __restrict__ feat,
    const float* __restrict__ Wc, const float* __restrict__ Wr, int N)
{
    const int lane = threadIdx.x & 31;
    const int warp = (blockIdx.x * blockDim.x + threadIdx.x) >> 5;
    const int nw   = (gridDim.x * blockDim.x) >> 5;

    // lane owns rows {lane*4+t} (t<4) and {128+lane*4+(t-4)} (t>=4)
    int rows[8];
#pragma unroll
    for (int t = 0; t < 8; t++) rows[t] = (t < 4) ? (lane * 4 + t) : (128 + lane * 4 + t - 4);

    float wd[8], wr[8][9];
#pragma unroll
    for (int t = 0; t < 8; t++) {
        wd[t] = Wc[rows[t] * 2 + 1] - Wc[rows[t] * 2 + 0];
#pragma unroll
        for (int j = 0; j < 9; j++) wr[t][j] = Wr[rows[t] * 9 + j];
    }

    float4 a0 = make_float4(0, 0, 0, 0), b0 = a0;
    if (warp < N) {
        const float4* f4 = (const float4*)(feat + (size_t)warp * 256);
        a0 = f4[lane]; b0 = f4[32 + lane];
    }
    for (int p = warp; p < N; p += nw) {
        int pn = p + nw;
        float4 a1 = make_float4(0, 0, 0, 0), b1 = a1;
        if (pn < N) {
            const float4* f4 = (const float4*)(feat + (size_t)pn * 256);
            a1 = f4[lane]; b1 = f4[32 + lane];
        }
        float fv[8] = {a0.x, a0.y, a0.z, a0.w, b0.x, b0.y, b0.z, b0.w};
        float acc[10];
#pragma unroll
        for (int j = 0; j < 10; j++) acc[j] = 0.f;
#pragma unroll
        for (int t = 0; t < 8; t++) {
            acc[0] = fmaf(fv[t], wd[t], acc[0]);
#pragma unroll
            for (int j = 0; j < 9; j++) acc[1 + j] = fmaf(fv[t], wr[t][j], acc[1 + j]);
        }
#pragma unroll
        for (int j = 0; j < 10; j++) {
#pragma unroll
            for (int o = 16; o > 0; o >>= 1)
                acc[j] += __shfl_xor_sync(0xFFFFFFFFu, acc[j], o);
        }
        if (lane == 0) {
            float* r = g_raw[p];
#pragma unroll
            for (int j = 0; j < 10; j++) r[j] = acc[j];
        }
        a0 = a1; b0 = b1;
    }
}

// ---------------- epilogue: thread per point (fp64 chains hidden by TLP) ----
__global__ void k_epilogue(
    const int* __restrict__ coor,
    const float* __restrict__ bc, const float* __restrict__ br, int N)
{
    int p = blockIdx.x * blockDim.x + threadIdx.x;
    if (p >= N) return;
    const float* r = g_raw[p];
    float dl = r[0] + (bc[1] - bc[0]);
    float rg[9];
#pragma unroll
    for (int j = 0; j < 9; j++) rg[j] = r[1 + j] + br[j];
    double sd = 1.0 / (1.0 + exp(-(double)dl));
    double ss = 1.0 / (1.0 + exp(-(double)rg[8]));
    float score = (float)(sd * ss);
    float cx = (float)coor[2 * p]     * 0.8f + rg[0];
    float cy = (float)coor[2 * p + 1] * 0.8f + rg[1];
    float bl = expf(fminf(fmaxf(rg[3], -6.f), 6.f));
    float bw = expf(fminf(fmaxf(rg[4], -6.f), 6.f));
    float bh = expf(fminf(fmaxf(rg[5], -6.f), 6.f));
    float an = atan2f(rg[6], rg[7]);
    float* bx = g_boxes[p];
    bx[0] = cx; bx[1] = cy; bx[2] = rg[2]; bx[3] = bl;
    bx[4] = bw; bx[5] = bh; bx[6] = an;  bx[7] = score;
    g_score[p] = __float_as_uint(score);
}

// ---------------- per-batch compaction ----------------
__global__ void k_compact(const int* __restrict__ bidx, int N)
{
    __shared__ int c[NB], base[NB];
    int t = threadIdx.x;
    if (t < NB) c[t] = 0;
    __syncthreads();
    int p = blockIdx.x * 1024 + t;
    int b = 0, r = 0;
    if (p < N) { b = bidx[p]; r = atomicAdd(&c[b], 1); }
    __syncthreads();
    if (t < NB) base[t] = atomicAdd(&g_cnt[t], c[t]);
    __syncthreads();
    if (p < N) {
        unsigned long long key =
            ((unsigned long long)g_score[p] << 32) | (unsigned)(~(unsigned)p);
        g_list[b][base[b] + r] = key;
    }
}

// ---------------- exact radix select top-1024 + bitonic sort ----------------
__global__ void k_select()
{
    const int b = blockIdx.x, tid = threadIdx.x;
    __shared__ unsigned int       hist[2048];
    __shared__ unsigned long long keys[KTOP];
    __shared__ unsigned long long sh_lo;
    __shared__ int sh_need, sh_done, sh_bin, sh_cnt;

    const int cnt = g_cnt[b];
    if (tid == 0) {
        sh_lo = 0ull; sh_need = KTOP; sh_cnt = 0;
        sh_done = (cnt <= KTOP) ? 1 : 0;
    }
    const int shifts[6] = {53, 42, 31, 20, 9, 0};
    const int widths[6] = {11, 11, 11, 11, 11, 9};

    for (int pass = 0; pass < 6; pass++) {
        __syncthreads();
        if (sh_done) break;
        for (int i = tid; i < 2048; i += 1024) hist[i] = 0;
        __syncthreads();
        const int shift = shifts[pass], w = widths[pass];
        const int nb = 1 << w;
        const unsigned long long hm =
            (shift + w >= 64) ? 0ull : ~((1ull << (shift + w)) - 1ull);
        const unsigned long long lo = sh_lo;
        const int need = sh_need;
        const unsigned mask = (unsigned)(nb - 1);
        for (int e = tid; e < cnt; e += 1024) {
            unsigned long long kk = g_list[b][e];
            if ((kk & hm) == lo)
                atomicAdd(&hist[(unsigned)(kk >> shift) & mask], 1u);
        }
        __syncthreads();
        for (int d = 1; d < nb; d <<= 1) {     // suffix sums
            unsigned v0 = 0, v1 = 0;
            int i0 = tid, i1 = tid + 1024;
            if (i0 < nb) v0 = hist[i0] + ((i0 + d < nb) ? hist[i0 + d] : 0u);
            if (i1 < nb) v1 = hist[i1] + ((i1 + d < nb) ? hist[i1 + d] : 0u);
            __syncthreads();
            if (i0 < nb) hist[i0] = v0;
            if (i1 < nb) hist[i1] = v1;
            __syncthreads();
        }
        for (int i = tid; i < nb; i += 1024) {
            unsigned s  = hist[i];
            unsigned sn = (i + 1 < nb) ? hist[i + 1] : 0u;
            if (s >= (unsigned)need && sn < (unsigned)need) sh_bin = i;
        }
        __syncthreads();
        if (tid == 0) {
            int bin = sh_bin;
            unsigned above = (bin + 1 < nb) ? hist[bin + 1] : 0u;
            unsigned cb = hist[bin] - above;
            sh_lo = lo | ((unsigned long long)bin << shift);
            int nd = need - (int)above;
            sh_need = nd;
            if ((unsigned)nd == cb) sh_done = 1;
        }
    }
    __syncthreads();
    const unsigned long long T = sh_lo;
    for (int e = tid; e < cnt; e += 1024) {
        unsigned long long kk = g_list[b][e];
        if (kk >= T) {
            int pos = atomicAdd(&sh_cnt, 1);
            if (pos < KTOP) keys[pos] = ~kk;    // inverted -> ascending == score desc
        }
    }
    __syncthreads();
    for (int i = tid; i < KTOP; i += 1024)
        if (i >= sh_cnt) keys[i] = ~0ull;
    __syncthreads();
    for (int k2 = 2; k2 <= KTOP; k2 <<= 1) {
        for (int j = k2 >> 1; j > 0; j >>= 1) {
            int ixj = tid ^ j;
            if (ixj > tid) {
                unsigned long long a = keys[tid], c2 = keys[ixj];
                bool up = ((tid & k2) == 0);
                if (up ? (a > c2) : (a < c2)) { keys[tid] = c2; keys[ixj] = a; }
            }
            __syncthreads();
        }
    }
    unsigned long long kv = ~keys[tid];
    float* o = g_sel[b][tid];
    if (kv != 0ull) {
        unsigned p = ~(unsigned)(kv & 0xFFFFFFFFull);
        const float* bx = g_boxes[p];
#pragma unroll
        for (int c2 = 0; c2 < 8; c2++) o[c2] = bx[c2];
    } else {
#pragma unroll
        for (int c2 = 0; c2 < 8; c2++) o[c2] = 0.f;
    }
}

__global__ void k_zero(float* out, int n) {
    int i = blockIdx.x * blockDim.x + threadIdx.x;
    if (i < n) out[i] = 0.f;
}

// ---------------- sparse-edge NMS + output assembly ----------------
__global__ void k_nms(float* __restrict__ out, int out_size)
{
    const int b = blockIdx.x, tid = threadIdx.x;
    __shared__ float sx1[KTOP], sx2[KTOP], sy1[KTOP], sy2[KTOP], sar[KTOP];
    __shared__ unsigned int edges[ECAP];
    __shared__ unsigned int suppw[KTOP / 32];
    __shared__ int ecnt;

    if (tid == 0) ecnt = 0;
    const float* s = g_sel[b][tid];
    float x = s[0], y = s[1], l = s[3], w = s[4];
    sx1[tid] = x - l * 0.5f; sx2[tid] = x + l * 0.5f;
    sy1[tid] = y - w * 0.5f; sy2[tid] = y + w * 0.5f;
    sar[tid] = l * w;
    __syncthreads();

    const float ax1 = sx1[tid], ax2 = sx2[tid];
    const float ay1 = sy1[tid], ay2 = sy2[tid], aa = sar[tid];
    for (int j = tid + 1; j < KTOP; j++) {
        float ix = fminf(ax2, sx2[j]) - fmaxf(ax1, sx1[j]);
        float iy = fminf(ay2, sy2[j]) - fmaxf(ay1, sy1[j]);
        ix = fmaxf(ix, 0.f); iy = fmaxf(iy, 0.f);
        float inter = ix * iy;
        float uni = aa + sar[j] - inter;
        float iou = inter / fmaxf(uni, 1e-6f);
        if (iou > 0.1f) {
            int e = atomicAdd(&ecnt, 1);
            if (e < ECAP) edges[e] = ((unsigned)tid << 10) | (unsigned)j;
        }
    }
    __syncthreads();
    if (tid == 0) {
        int E = ecnt < ECAP ? ecnt : ECAP;
        for (int i = 1; i < E; i++) {       // insertion sort (E ~ tens)
            unsigned v = edges[i]; int k = i - 1;
            while (k >= 0 && edges[k] > v) { edges[k + 1] = edges[k]; k--; }
            edges[k + 1] = v;
        }
        unsigned sw[KTOP / 32];
#pragma unroll
        for (int i2 = 0; i2 < KTOP / 32; i2++) sw[i2] = 0u;
        for (int e = 0; e < E; e++) {
            unsigned v = edges[e];
            int i2 = v >> 10, j2 = v & 1023;
            if (!((sw[i2 >> 5] >> (i2 & 31)) & 1u))
                sw[j2 >> 5] |= 1u << (j2 & 31);
        }
#pragma unroll
        for (int i2 = 0; i2 < KTOP / 32; i2++) suppw[i2] = sw[i2];
    }
    __syncthreads();
    bool keep = !((suppw[tid >> 5] >> (tid & 31)) & 1u);
    float km = keep ? 1.f : 0.f;
    int row = b * KTOP + tid;
    int obase = row * 8;
    if (obase + 7 < out_size) {
#pragma unroll
        for (int c = 0; c < 8; c++) out[obase + c] = s[c] * km;
    }
    int lb_i = NB * KTOP * 8 + row;
    int kp_i = NB * KTOP * 9 + row;
    if (lb_i < out_size) out[lb_i] = 0.f;
    if (kp_i < out_size) out[kp_i] = km;
}

extern "C" void kernel_launch(void* const* d_in, const int* in_sizes, int n_in,
                              void* d_out, int out_size)
{
    const float* feat = (const float*)d_in[0];
    const int*   bidx = (const int*)d_in[1];
    const int*   coor = (const int*)d_in[2];
    const float* Wc   = (const float*)d_in[3];
    const float* bc   = (const float*)d_in[4];
    const float* Wr   = (const float*)d_in[5];
    const float* br   = (const float*)d_in[6];
    float* out = (float*)d_out;
    int N = in_sizes[1];

    k_init<<<1, 32>>>();
    k_gemv<<<592, 256>>>(feat, Wc, Wr, N);
    k_epilogue<<<(N + 255) / 256, 256>>>(coor, bc, br, N);
    k_compact<<<(N + 1023) / 1024, 1024>>>(bidx, N);
    k_select<<<NB, 1024>>>();
    k_zero<<<(out_size + 255) / 256, 256>>>(out, out_size);
    k_nms<<<NB, 1024>>>(out, out_size);
}